// round 11
// baseline (speedup 1.0000x reference)
#include <cuda_runtime.h>
#include <cuda_bf16.h>
#include <math.h>
#include <stdint.h>

// Problem constants
#define BB 32
#define SS 4096
#define KD 512
#define HD 512
#define NEGV (-1e9f)
#define MARGIN 0.125f
#define MAXCAND 512
#define VHALF (BB*SS*KD)     // elements per head in V

// Output layout: [att_vector (32*512) | al_a (32*4096) | al_b (32*4096)]
#define OUT_ATT 0
#define OUT_AL  (BB*HD)

// Scratch (device globals; no allocations allowed)
__device__ float g_pq[2][BB][HD];
__device__ float g_scp[4][2][BB][SS];     // per-nh partial approx scores
__device__ float g_scores[2][BB][SS];     // masked -> refined scores
__device__ float g_ctx[2][BB][KD];
__device__ int   g_mask_mode;
__device__ __nv_bfloat16 g_Bt[2][HD][KD]; // transposed bf16 Wk: g_Bt[h][n][k]
__device__ __nv_bfloat16 g_Vb[2][BB][SS][KD]; // bf16 copy of values (256 MB)
__device__ int   g_cand[2][BB][MAXCAND];
__device__ int   g_ccnt[2][BB];

// ---------------------------------------------------------------------------
__device__ __forceinline__ float tanh_fast(float x) {
    float cx = fminf(fmaxf(x, -15.0f), 15.0f);
    float e = __expf(2.0f * cx);
    return __fdividef(e - 1.0f, e + 1.0f);
}

__device__ __forceinline__ uint32_t smem_u32(const void* p) {
    uint32_t a;
    asm("{ .reg .u64 t; cvta.to.shared.u64 t, %1; cvt.u32.u64 %0, t; }"
        : "=r"(a) : "l"(p));
    return a;
}

__device__ __forceinline__ uint32_t pack_bf2(float x0, float x1) {
    uint32_t d;
    asm("cvt.rn.satfinite.bf16x2.f32 %0, %1, %2;" : "=r"(d) : "f"(x1), "f"(x0));
    return d;
}

__device__ __forceinline__ void ldsm4(uint32_t& r0, uint32_t& r1,
                                      uint32_t& r2, uint32_t& r3, uint32_t a) {
    asm volatile("ldmatrix.sync.aligned.m8n8.x4.shared.b16 {%0,%1,%2,%3}, [%4];"
                 : "=r"(r0), "=r"(r1), "=r"(r2), "=r"(r3) : "r"(a));
}

__device__ __forceinline__ void mma_bf16(float* c, const uint32_t* a,
                                         const uint32_t* b) {
    asm volatile(
        "mma.sync.aligned.m16n8k16.row.col.f32.bf16.bf16.f32 "
        "{%0,%1,%2,%3}, {%4,%5,%6,%7}, {%8,%9}, {%0,%1,%2,%3};"
        : "+f"(c[0]), "+f"(c[1]), "+f"(c[2]), "+f"(c[3])
        : "r"(a[0]), "r"(a[1]), "r"(a[2]), "r"(a[3]), "r"(b[0]), "r"(b[1]));
}

__device__ __forceinline__ void cp_async16(uint32_t saddr, const void* gptr) {
    asm volatile("cp.async.cg.shared.global [%0], [%1], 16;"
                 :: "r"(saddr), "l"(gptr) : "memory");
}
#define CP_COMMIT() asm volatile("cp.async.commit_group;" ::: "memory")
#define CP_WAIT0()  asm volatile("cp.async.wait_group 0;" ::: "memory")

// Cross-block reduce helper (512 threads, 16 warps)
__device__ __forceinline__ float block_sum(float v, float* wred, float* bcast,
                                           int lane, int wid, int tid) {
    #pragma unroll
    for (int off = 16; off > 0; off >>= 1)
        v += __shfl_xor_sync(0xffffffffu, v, off);
    if (lane == 0) wred[wid] = v;
    __syncthreads();
    if (tid == 0) {
        float tot = 0.0f;
        #pragma unroll
        for (int w = 0; w < 16; w++) tot += wred[w];
        *bcast = tot;
    }
    __syncthreads();
    float r = *bcast;
    __syncthreads();
    return r;
}

// ---------------------------------------------------------------------------
// prep_all: fused independent preprocessing, 256 threads/block.
#define PREP_V_BLOCKS 8192
#define PREP_GRID (69 + PREP_V_BLOCKS)

__global__ __launch_bounds__(256)
void prep_all_kernel(const float* __restrict__ query,
                     const float* __restrict__ values_a,
                     const float* __restrict__ values_b,
                     const unsigned char* __restrict__ mask_raw,
                     const float* __restrict__ Wk_a,
                     const float* __restrict__ Wk_b,
                     const float* __restrict__ Wq_a,
                     const float* __restrict__ Wq_b) {
    int bid = blockIdx.x;
    int tid = threadIdx.x;

    if (bid >= 69) {
        // ---- V -> bf16 ----
        int vb = bid - 69;
        #pragma unroll
        for (int i = 0; i < 8; i++) {
            size_t op = ((size_t)vb * 8 + i) * 256 + tid;
            size_t e = op * 8;
            int head = e >= (size_t)VHALF;
            size_t off = e - (size_t)head * VHALF;
            const float* src = head ? values_b : values_a;
            float4 a = *(const float4*)(src + off);
            float4 c = *(const float4*)(src + off + 4);
            uint4 o;
            o.x = pack_bf2(a.x, a.y); o.y = pack_bf2(a.z, a.w);
            o.z = pack_bf2(c.x, c.y); o.w = pack_bf2(c.z, c.w);
            ((uint4*)g_Vb)[op] = o;
        }
    } else if (bid == 0) {
        __shared__ int c[4];
        if (tid < 4) c[tid] = 0;
        __syncthreads();
        int local[4] = {0, 0, 0, 0};
        for (int i = tid; i < 32768; i += 256)
            if (mask_raw[i]) local[i & 3]++;
        #pragma unroll
        for (int j = 0; j < 4; j++) if (local[j]) atomicAdd(&c[j], local[j]);
        __syncthreads();
        if (tid == 0) {
            int mode;
            if (c[1] > 0)      mode = 0;
            else if (c[0] > 0) mode = 1;
            else               mode = 2;
            g_mask_mode = mode;
        }
    } else if (bid <= 4) {
        int gid = (bid - 1) * 256 + tid;
        int head = gid >> 9;
        int n = gid & 511;
        const float* Wk = head ? Wk_b : Wk_a;
        #pragma unroll 2
        for (int kc = 0; kc < 64; kc++) {
            float x[8];
            #pragma unroll
            for (int j = 0; j < 8; j++)
                x[j] = Wk[(size_t)(kc * 8 + j) * HD + n];
            uint4 o;
            o.x = pack_bf2(x[0], x[1]); o.y = pack_bf2(x[2], x[3]);
            o.z = pack_bf2(x[4], x[5]); o.w = pack_bf2(x[6], x[7]);
            *(uint4*)(&g_Bt[head][n][kc * 8]) = o;
        }
    } else {
        int zb = bid - 5;
        int head = zb >> 5;
        int b    = zb & 31;
        const float* Wq = head ? Wq_b : Wq_a;
        __shared__ float q[HD];
        __shared__ float part[4][HD];
        q[tid] = query[b * HD + tid];
        q[tid + 256] = query[b * HD + tid + 256];
        __syncthreads();
        int kq = tid >> 6;
        int hg = (tid & 63) * 8;
        float acc[8];
        #pragma unroll
        for (int j = 0; j < 8; j++) acc[j] = 0.0f;
        const float* Wbase = Wq + (size_t)(kq * 128) * HD + hg;
        #pragma unroll 2
        for (int k = 0; k < 128; k++) {
            float qk = q[kq * 128 + k];
            float4 w0 = *(const float4*)(Wbase + (size_t)k * HD);
            float4 w1 = *(const float4*)(Wbase + (size_t)k * HD + 4);
            acc[0] = fmaf(qk, w0.x, acc[0]); acc[1] = fmaf(qk, w0.y, acc[1]);
            acc[2] = fmaf(qk, w0.z, acc[2]); acc[3] = fmaf(qk, w0.w, acc[3]);
            acc[4] = fmaf(qk, w1.x, acc[4]); acc[5] = fmaf(qk, w1.y, acc[5]);
            acc[6] = fmaf(qk, w1.z, acc[6]); acc[7] = fmaf(qk, w1.w, acc[7]);
        }
        *(float4*)&part[kq][hg]     = make_float4(acc[0], acc[1], acc[2], acc[3]);
        *(float4*)&part[kq][hg + 4] = make_float4(acc[4], acc[5], acc[6], acc[7]);
        __syncthreads();
        g_pq[head][b][tid] = (part[0][tid] + part[1][tid]) +
                             (part[2][tid] + part[3][tid]);
        int t2 = tid + 256;
        g_pq[head][b][t2] = (part[0][t2] + part[1][t2]) +
                            (part[2][t2] + part[3][t2]);
    }
}

// ---------------------------------------------------------------------------
// Hot kernel: bf16 mma.sync GEMM; A and B both via cp.async (unchanged R9).
#define SMA0 0
#define SMA1 18432
#define SMB0 36864
#define SMB1 55296
#define SM_PS  73728
#define SM_VS  74240
#define SM_RED 74752
#define SM_TOTAL 76800

__global__ __launch_bounds__(256, 2)
void score_mma_kernel(const float* __restrict__ v_a,
                      const float* __restrict__ v_b) {
    int sc = blockIdx.x;
    int nh = blockIdx.y;
    int zb = blockIdx.z;
    int head = zb >> 5;
    int b    = zb & 31;
    const float* vv = head ? v_b : v_a;

    extern __shared__ char smem[];
    uint32_t sb = smem_u32(smem);
    int tid = threadIdx.x, lane = tid & 31, wid = tid >> 5;
    int warp_m = wid & 1, warp_n = wid >> 1;

    float acc[4][4][4];
    #pragma unroll
    for (int mf = 0; mf < 4; mf++)
        #pragma unroll
        for (int nf = 0; nf < 4; nf++)
            #pragma unroll
            for (int r = 0; r < 4; r++) acc[mf][nf][r] = 0.0f;

    const __nv_bfloat16* Asrc = &g_Vb[head][b][sc * 128][0];
    const __nv_bfloat16* Bsrc = &g_Bt[head][nh * 128][0];

    int sr[4], sg[4];
    #pragma unroll
    for (int i = 0; i < 4; i++) {
        int idx = i * 256 + tid;
        sr[i] = idx >> 3;
        sg[i] = idx & 7;
    }

    uint32_t aRow = (uint32_t)(warp_m * 64 + (lane & 15));
    uint32_t aColB = (uint32_t)((lane >> 4) * 16);
    uint32_t bRow = (uint32_t)(warp_n * 32 + (lane & 7) + ((lane >> 4) & 1) * 8);
    uint32_t bColB = (uint32_t)(((lane >> 3) & 1) * 16);

    #pragma unroll
    for (int i = 0; i < 4; i++) {
        cp_async16(sb + SMA0 + sr[i] * 144 + sg[i] * 16,
                   Asrc + (size_t)sr[i] * KD + sg[i] * 8);
        cp_async16(sb + SMB0 + sr[i] * 144 + sg[i] * 16,
                   Bsrc + (size_t)sr[i] * KD + sg[i] * 8);
    }
    CP_COMMIT();
    CP_WAIT0();
    __syncthreads();

    for (int kc = 0; kc < 8; kc++) {
        int cur = kc & 1;
        uint32_t Ab = sb + (cur ? SMA1 : SMA0);
        uint32_t Bb = sb + (cur ? SMB1 : SMB0);
        uint32_t An = sb + (cur ? SMA0 : SMA1);
        uint32_t Bn = sb + (cur ? SMB0 : SMB1);
        if (kc < 7) {
            #pragma unroll
            for (int i = 0; i < 4; i++) {
                cp_async16(An + sr[i] * 144 + sg[i] * 16,
                           Asrc + (size_t)sr[i] * KD + (kc + 1) * 64 + sg[i] * 8);
                cp_async16(Bn + sr[i] * 144 + sg[i] * 16,
                           Bsrc + (size_t)sr[i] * KD + (kc + 1) * 64 + sg[i] * 8);
            }
            CP_COMMIT();
        }
        #pragma unroll
        for (int ks = 0; ks < 4; ks++) {
            uint32_t af[4][4], bf[2][4];
            #pragma unroll
            for (int mf = 0; mf < 4; mf++) {
                uint32_t off = (aRow + mf * 16) * 144 + ks * 32 + aColB;
                ldsm4(af[mf][0], af[mf][1], af[mf][2], af[mf][3], Ab + off);
            }
            #pragma unroll
            for (int p = 0; p < 2; p++) {
                uint32_t off = (bRow + p * 16) * 144 + ks * 32 + bColB;
                ldsm4(bf[p][0], bf[p][1], bf[p][2], bf[p][3], Bb + off);
            }
            #pragma unroll
            for (int mf = 0; mf < 4; mf++)
                #pragma unroll
                for (int p = 0; p < 2; p++) {
                    mma_bf16(acc[mf][2 * p + 0], af[mf], &bf[p][0]);
                    mma_bf16(acc[mf][2 * p + 1], af[mf], &bf[p][2]);
                }
        }
        if (kc < 7) CP_WAIT0();
        __syncthreads();
    }

    float* ps  = (float*)(smem + SM_PS);
    float* vs  = (float*)(smem + SM_VS);
    float* red = (float*)(smem + SM_RED);
    if (tid < 128) {
        ps[tid] = g_pq[head][b][nh * 128 + tid];
        vs[tid] = vv[nh * 128 + tid];
    }
    __syncthreads();

    #pragma unroll
    for (int mf = 0; mf < 4; mf++) {
        float slo = 0.0f, shi = 0.0f;
        #pragma unroll
        for (int nf = 0; nf < 4; nf++) {
            int h = warp_n * 32 + nf * 8 + (lane & 3) * 2;
            slo = fmaf(vs[h],     tanh_fast(acc[mf][nf][0] + ps[h]),     slo);
            slo = fmaf(vs[h + 1], tanh_fast(acc[mf][nf][1] + ps[h + 1]), slo);
            shi = fmaf(vs[h],     tanh_fast(acc[mf][nf][2] + ps[h]),     shi);
            shi = fmaf(vs[h + 1], tanh_fast(acc[mf][nf][3] + ps[h + 1]), shi);
        }
        slo += __shfl_xor_sync(0xffffffffu, slo, 1);
        slo += __shfl_xor_sync(0xffffffffu, slo, 2);
        shi += __shfl_xor_sync(0xffffffffu, shi, 1);
        shi += __shfl_xor_sync(0xffffffffu, shi, 2);
        if ((lane & 3) == 0) {
            int row = warp_m * 64 + mf * 16 + (lane >> 2);
            red[row * 4 + warp_n]       = slo;
            red[(row + 8) * 4 + warp_n] = shi;
        }
    }
    __syncthreads();
    if (tid < 128) {
        float s = (red[tid * 4 + 0] + red[tid * 4 + 1]) +
                  (red[tid * 4 + 2] + red[tid * 4 + 3]);
        g_scp[nh][head][b][sc * 128 + tid] = s;
    }
}

// ---------------------------------------------------------------------------
// Pass 1: register-resident bisect (16 iters; MARGIN covers the slack).
__global__ void spmax_pass1_kernel(const void* __restrict__ ma,
                                   const void* __restrict__ mb) {
    int head = blockIdx.x >> 5;
    int b    = blockIdx.x & 31;
    const void* mp = head ? mb : ma;
    int mode = g_mask_mode;

    __shared__ float wred[16];
    __shared__ float bcast;
    __shared__ int scnt;

    int tid  = threadIdx.x;
    int lane = tid & 31;
    int wid  = tid >> 5;
    if (tid == 0) scnt = 0;
    int i0 = tid * 8;

    float zr[8];
    #pragma unroll
    for (int j = 0; j < 8; j++) zr[j] = 0.0f;
    #pragma unroll
    for (int nh = 0; nh < 4; nh++) {
        const float4* p = (const float4*)&g_scp[nh][head][b][i0];
        float4 a = p[0], c = p[1];
        zr[0] += a.x; zr[1] += a.y; zr[2] += a.z; zr[3] += a.w;
        zr[4] += c.x; zr[5] += c.y; zr[6] += c.z; zr[7] += c.w;
    }
    if (mode == 1) {
        const int4* p = (const int4*)((const int*)mp + b * SS + i0);
        int4 m0 = p[0], m1 = p[1];
        int mm[8] = {m0.x, m0.y, m0.z, m0.w, m1.x, m1.y, m1.z, m1.w};
        #pragma unroll
        for (int j = 0; j < 8; j++) if (!mm[j]) zr[j] = NEGV;
    } else if (mode == 0) {
        const unsigned char* p = (const unsigned char*)mp + b * SS + i0;
        #pragma unroll
        for (int j = 0; j < 8; j++) if (!p[j]) zr[j] = NEGV;
    } else {
        const float4* p = (const float4*)((const float*)mp + b * SS + i0);
        float4 m0 = p[0], m1 = p[1];
        float mm[8] = {m0.x, m0.y, m0.z, m0.w, m1.x, m1.y, m1.z, m1.w};
        #pragma unroll
        for (int j = 0; j < 8; j++) if (mm[j] == 0.0f) zr[j] = NEGV;
    }
    {
        float4* q = (float4*)&g_scores[head][b][i0];
        q[0] = make_float4(zr[0], zr[1], zr[2], zr[3]);
        q[1] = make_float4(zr[4], zr[5], zr[6], zr[7]);
    }

    float lmax = zr[0];
    #pragma unroll
    for (int j = 1; j < 8; j++) lmax = fmaxf(lmax, zr[j]);
    #pragma unroll
    for (int off = 16; off > 0; off >>= 1)
        lmax = fmaxf(lmax, __shfl_xor_sync(0xffffffffu, lmax, off));
    if (lane == 0) wred[wid] = lmax;
    __syncthreads();
    if (tid == 0) {
        float m = wred[0];
        for (int w = 1; w < 16; w++) m = fmaxf(m, wred[w]);
        bcast = m;
    }
    __syncthreads();
    float zmax = bcast;
    __syncthreads();

    float lo = zmax - 1.0f, hi = zmax;
    for (int it = 0; it < 16; it++) {
        float mid = 0.5f * (lo + hi);
        float s = 0.0f;
        #pragma unroll
        for (int j = 0; j < 8; j++) s += fmaxf(zr[j] - mid, 0.0f);
        float tot = block_sum(s, wred, &bcast, lane, wid, tid);
        if (tot >= 1.0f) lo = mid; else hi = mid;
    }
    float tau = 0.5f * (lo + hi);

    float thr = tau - MARGIN;
    #pragma unroll
    for (int j = 0; j < 8; j++) {
        if (zr[j] > thr) {
            int p = atomicAdd(&scnt, 1);
            if (p < MAXCAND) g_cand[head][b][p] = i0 + j;
        }
    }
    __syncthreads();
    if (tid == 0) g_ccnt[head][b] = scnt < MAXCAND ? scnt : MAXCAND;
}

// ---------------------------------------------------------------------------
// Refine v3: v1 structure (coalesced scalar Wk), 8-way candidate split.
// Grid 512 = (head, b, oct). 256 threads. Batch 4 candidate rows.
// Per k: 2 LDG + 4 LDS + 8 FMA (halved stream vs v1, 2x occupancy).
__global__ __launch_bounds__(256)
void refine_kernel(const float* __restrict__ values_a,
                   const float* __restrict__ values_b,
                   const float* __restrict__ Wk_a,
                   const float* __restrict__ Wk_b,
                   const float* __restrict__ v_a,
                   const float* __restrict__ v_b) {
    int head = blockIdx.x >> 8;
    int b    = (blockIdx.x >> 3) & 31;
    int oct  = blockIdx.x & 7;
    const float* V  = head ? values_b : values_a;
    const float* Wk = head ? Wk_b : Wk_a;
    const float* vv = head ? v_b : v_a;

    __shared__ float vrow[4][512];   // 8 KB
    __shared__ float red[4][8];

    int t = threadIdx.x, lane = t & 31, wid = t >> 5;
    float pq0 = g_pq[head][b][t], pq1 = g_pq[head][b][t + 256];
    float vv0 = vv[t], vv1 = vv[t + 256];

    int cnt = g_ccnt[head][b];
    // this block handles candidate positions p ≡ oct (mod 8), 4 per batch
    for (int base = oct; base < cnt; base += 32) {
        #pragma unroll
        for (int g = 0; g < 4; g++) {
            int ci = base + g * 8;
            if (ci < cnt) {
                int row = g_cand[head][b][ci];
                const float* src = V + ((size_t)b * SS + row) * KD;
                vrow[g][t] = src[t];
                vrow[g][t + 256] = src[t + 256];
            } else {
                vrow[g][t] = 0.0f;
                vrow[g][t + 256] = 0.0f;
            }
        }
        __syncthreads();

        float a0[4], a1[4];
        #pragma unroll
        for (int g = 0; g < 4; g++) { a0[g] = 0.0f; a1[g] = 0.0f; }
        #pragma unroll 4
        for (int k = 0; k < 512; k++) {
            float w0 = Wk[k * HD + t];
            float w1 = Wk[k * HD + t + 256];
            #pragma unroll
            for (int g = 0; g < 4; g++) {
                float x = vrow[g][k];
                a0[g] = fmaf(x, w0, a0[g]);
                a1[g] = fmaf(x, w1, a1[g]);
            }
        }
        #pragma unroll
        for (int g = 0; g < 4; g++) {
            float s = vv0 * tanh_fast(pq0 + a0[g]) + vv1 * tanh_fast(pq1 + a1[g]);
            #pragma unroll
            for (int off = 16; off > 0; off >>= 1)
                s += __shfl_xor_sync(0xffffffffu, s, off);
            if (lane == 0) red[g][wid] = s;
        }
        __syncthreads();
        if (t < 4) {
            int ci = base + t * 8;
            if (ci < cnt) {
                float s = 0.0f;
                #pragma unroll
                for (int w = 0; w < 8; w++) s += red[t][w];
                g_scores[head][b][g_cand[head][b][ci]] = s;
            }
        }
        __syncthreads();
    }
}

// ---------------------------------------------------------------------------
// Pass 2: register-resident bisect (30 iters) + compact context.
__global__ void sparsemax_kernel(const float* __restrict__ values_a,
                                 const float* __restrict__ values_b,
                                 float* __restrict__ out) {
    int head = blockIdx.x >> 5;
    int b    = blockIdx.x & 31;
    const float* V = head ? values_b : values_a;

    __shared__ float wred[16];
    __shared__ float bcast;
    __shared__ int   sidx[MAXCAND];
    __shared__ float sal[MAXCAND];
    __shared__ int   snum;

    int tid  = threadIdx.x;
    int lane = tid & 31;
    int wid  = tid >> 5;
    if (tid == 0) snum = 0;
    int i0 = tid * 8;

    float zr[8];
    {
        const float4* p = (const float4*)&g_scores[head][b][i0];
        float4 a = p[0], c = p[1];
        zr[0] = a.x; zr[1] = a.y; zr[2] = a.z; zr[3] = a.w;
        zr[4] = c.x; zr[5] = c.y; zr[6] = c.z; zr[7] = c.w;
    }

    float lmax = zr[0];
    #pragma unroll
    for (int j = 1; j < 8; j++) lmax = fmaxf(lmax, zr[j]);
    #pragma unroll
    for (int off = 16; off > 0; off >>= 1)
        lmax = fmaxf(lmax, __shfl_xor_sync(0xffffffffu, lmax, off));
    if (lane == 0) wred[wid] = lmax;
    __syncthreads();
    if (tid == 0) {
        float m = wred[0];
        for (int w = 1; w < 16; w++) m = fmaxf(m, wred[w]);
        bcast = m;
    }
    __syncthreads();
    float zmax = bcast;
    __syncthreads();

    float lo = zmax - 1.0f, hi = zmax;
    for (int it = 0; it < 30; it++) {
        float mid = 0.5f * (lo + hi);
        float s = 0.0f;
        #pragma unroll
        for (int j = 0; j < 8; j++) s += fmaxf(zr[j] - mid, 0.0f);
        float tot = block_sum(s, wred, &bcast, lane, wid, tid);
        if (tot >= 1.0f) lo = mid; else hi = mid;
    }
    float tau = 0.5f * (lo + hi);

    float* alout = out + OUT_AL + (size_t)head * BB * SS + (size_t)b * SS;
    float al[8];
    #pragma unroll
    for (int j = 0; j < 8; j++) al[j] = fmaxf(zr[j] - tau, 0.0f);
    {
        float4* q = (float4*)(alout + i0);
        q[0] = make_float4(al[0], al[1], al[2], al[3]);
        q[1] = make_float4(al[4], al[5], al[6], al[7]);
    }
    #pragma unroll
    for (int j = 0; j < 8; j++) {
        if (al[j] > 0.0f) {
            int p = atomicAdd(&snum, 1);
            if (p < MAXCAND) { sidx[p] = i0 + j; sal[p] = al[j]; }
        }
    }
    __syncthreads();

    const float* Vb = V + (size_t)b * SS * KD;
    float ctx = 0.0f;
    int ns = snum;
    if (ns <= MAXCAND) {
        for (int j = 0; j < ns; j++)
            ctx = fmaf(sal[j], Vb[(size_t)sidx[j] * KD + tid], ctx);
    } else {
        for (int s = 0; s < SS; s++) {
            float a = alout[s];
            if (a > 0.0f) ctx = fmaf(a, Vb[(size_t)s * KD + tid], ctx);
        }
    }
    g_ctx[head][b][tid] = ctx;
}

// ---------------------------------------------------------------------------
// Merge: gate softmax + candidates + blend. (h-quad x k-quarter) layout.
__global__ void merge_kernel(const float* __restrict__ query,
                             const float* __restrict__ Wg,
                             const float* __restrict__ bg,
                             const float* __restrict__ Wu_a,
                             const float* __restrict__ bu_a,
                             const float* __restrict__ Wu_b,
                             const float* __restrict__ bu_b,
                             float* __restrict__ out) {
    int b = blockIdx.x;
    int t = threadIdx.x;
    int lane = t & 31, wid = t >> 5;
    __shared__ float qv[HD], ca[KD], cb[KD];
    __shared__ float part_a[4][HD], part_b[4][HD];
    __shared__ float red0[16], red1[16];
    __shared__ float w01[2];

    qv[t] = query[b * HD + t];
    ca[t] = g_ctx[0][b][t];
    cb[t] = g_ctx[1][b][t];
    __syncthreads();

    float p0 = 0.0f, p1 = 0.0f;
    {
        float x = qv[t];
        p0 = fmaf(x, Wg[t * 2 + 0], p0);  p1 = fmaf(x, Wg[t * 2 + 1], p1);
        x = ca[t];
        p0 = fmaf(x, Wg[(512 + t) * 2 + 0], p0);  p1 = fmaf(x, Wg[(512 + t) * 2 + 1], p1);
        x = cb[t];
        p0 = fmaf(x, Wg[(1024 + t) * 2 + 0], p0); p1 = fmaf(x, Wg[(1024 + t) * 2 + 1], p1);
    }
    #pragma unroll
    for (int off = 16; off > 0; off >>= 1) {
        p0 += __shfl_xor_sync(0xffffffffu, p0, off);
        p1 += __shfl_xor_sync(0xffffffffu, p1, off);
    }
    if (lane == 0) { red0[wid] = p0; red1[wid] = p1; }
    __syncthreads();
    if (t == 0) {
        float g0 = bg[0], g1 = bg[1];
        for (int w = 0; w < 16; w++) { g0 += red0[w]; g1 += red1[w]; }
        float m = fmaxf(g0, g1);
        float e0 = expf(g0 - m), e1 = expf(g1 - m);
        float inv = 1.0f / (e0 + e1);
        w01[0] = e0 * inv;
        w01[1] = e1 * inv;
    }
    __syncthreads();

    int hq = (t & 127) * 4;
    int kq = t >> 7;
    const float* xa_seg = (kq < 2) ? (qv + kq * 256) : (ca + (kq - 2) * 256);
    const float* xb_seg = (kq < 2) ? (qv + kq * 256) : (cb + (kq - 2) * 256);
    const float* Wua = Wu_a + (size_t)(kq * 256) * HD + hq;
    const float* Wub = Wu_b + (size_t)(kq * 256) * HD + hq;
    float4 aa = make_float4(0.f, 0.f, 0.f, 0.f);
    float4 ab = make_float4(0.f, 0.f, 0.f, 0.f);
    #pragma unroll 2
    for (int i = 0; i < 256; i++) {
        float xa = xa_seg[i], xb = xb_seg[i];
        float4 wa = *(const float4*)(Wua + (size_t)i * HD);
        float4 wb = *(const float4*)(Wub + (size_t)i * HD);
        aa.x = fmaf(xa, wa.x, aa.x); aa.y = fmaf(xa, wa.y, aa.y);
        aa.z = fmaf(xa, wa.z, aa.z); aa.w = fmaf(xa, wa.w, aa.w);
        ab.x = fmaf(xb, wb.x, ab.x); ab.y = fmaf(xb, wb.y, ab.y);
        ab.z = fmaf(xb, wb.z, ab.z); ab.w = fmaf(xb, wb.w, ab.w);
    }
    *(float4*)&part_a[kq][hq] = aa;
    *(float4*)&part_b[kq][hq] = ab;
    __syncthreads();

    float w0 = w01[0], w1 = w01[1];
    float sa = bu_a[t] + (part_a[0][t] + part_a[1][t]) + (part_a[2][t] + part_a[3][t]);
    float sb = bu_b[t] + (part_b[0][t] + part_b[1][t]) + (part_b[2][t] + part_b[3][t]);
    out[OUT_ATT + b * HD + t] = w0 * tanhf(sa) + w1 * tanhf(sb);
}

// ---------------------------------------------------------------------------
extern "C" void kernel_launch(void* const* d_in, const int* in_sizes, int n_in,
                              void* d_out, int out_size) {
    const float* query    = (const float*)d_in[0];
    const float* values_a = (const float*)d_in[1];
    const float* values_b = (const float*)d_in[2];
    const void*  mask_a   = d_in[3];
    const void*  mask_b   = d_in[4];
    const float* Wk_a = (const float*)d_in[5];
    const float* Wq_a = (const float*)d_in[6];
    const float* v_a  = (const float*)d_in[7];
    const float* Wk_b = (const float*)d_in[8];
    const float* Wq_b = (const float*)d_in[9];
    const float* v_b  = (const float*)d_in[10];
    const float* Wg   = (const float*)d_in[11];
    const float* bg   = (const float*)d_in[12];
    const float* Wu_a = (const float*)d_in[13];
    const float* bu_a = (const float*)d_in[14];
    const float* Wu_b = (const float*)d_in[15];
    const float* bu_b = (const float*)d_in[16];
    float* out = (float*)d_out;

    cudaFuncSetAttribute(score_mma_kernel,
                         cudaFuncAttributeMaxDynamicSharedMemorySize, SM_TOTAL);

    prep_all_kernel<<<PREP_GRID, 256>>>(query, values_a, values_b,
                                        (const unsigned char*)mask_a,
                                        Wk_a, Wk_b, Wq_a, Wq_b);
    dim3 g1(32, 4, 64);
    score_mma_kernel<<<g1, 256, SM_TOTAL>>>(v_a, v_b);
    spmax_pass1_kernel<<<64, 512>>>(mask_a, mask_b);
    refine_kernel<<<512, 256>>>(values_a, values_b, Wk_a, Wk_b, v_a, v_b);
    sparsemax_kernel<<<64, 512>>>(values_a, values_b, out);
    merge_kernel<<<32, 512>>>(query, Wg, bg, Wu_a, bu_a, Wu_b, bu_b, out);
}

// round 12
// speedup vs baseline: 1.1402x; 1.1402x over previous
#include <cuda_runtime.h>
#include <cuda_bf16.h>
#include <math.h>
#include <stdint.h>

// Problem constants
#define BB 32
#define SS 4096
#define KD 512
#define HD 512
#define NEGV (-1e9f)
#define MARGIN 0.125f
#define MAXCAND 512
#define VHALF (BB*SS*KD)     // elements per head in V

// Output layout: [att_vector (32*512) | al_a (32*4096) | al_b (32*4096)]
#define OUT_ATT 0
#define OUT_AL  (BB*HD)

// Scratch (device globals; no allocations allowed)
__device__ float g_pq[2][BB][HD];
__device__ float g_scp[4][2][BB][SS];     // per-nh partial approx scores
__device__ float g_scores[2][BB][SS];     // masked -> refined scores
__device__ float g_ctx[2][BB][KD];
__device__ int   g_mask_mode;
__device__ __nv_bfloat16 g_Bt[2][HD][KD]; // transposed bf16 Wk: g_Bt[h][n][k]
__device__ __nv_bfloat16 g_Vb[2][BB][SS][KD]; // bf16 copy of values (256 MB)
__device__ int   g_cand[2][BB][MAXCAND];
__device__ int   g_ccnt[2][BB];

// ---------------------------------------------------------------------------
__device__ __forceinline__ float tanh_fast(float x) {
    float cx = fminf(fmaxf(x, -15.0f), 15.0f);
    float e = __expf(2.0f * cx);
    return __fdividef(e - 1.0f, e + 1.0f);
}

__device__ __forceinline__ uint32_t smem_u32(const void* p) {
    uint32_t a;
    asm("{ .reg .u64 t; cvta.to.shared.u64 t, %1; cvt.u32.u64 %0, t; }"
        : "=r"(a) : "l"(p));
    return a;
}

__device__ __forceinline__ uint32_t pack_bf2(float x0, float x1) {
    uint32_t d;
    asm("cvt.rn.satfinite.bf16x2.f32 %0, %1, %2;" : "=r"(d) : "f"(x1), "f"(x0));
    return d;
}

__device__ __forceinline__ void ldsm4(uint32_t& r0, uint32_t& r1,
                                      uint32_t& r2, uint32_t& r3, uint32_t a) {
    asm volatile("ldmatrix.sync.aligned.m8n8.x4.shared.b16 {%0,%1,%2,%3}, [%4];"
                 : "=r"(r0), "=r"(r1), "=r"(r2), "=r"(r3) : "r"(a));
}

__device__ __forceinline__ void mma_bf16(float* c, const uint32_t* a,
                                         const uint32_t* b) {
    asm volatile(
        "mma.sync.aligned.m16n8k16.row.col.f32.bf16.bf16.f32 "
        "{%0,%1,%2,%3}, {%4,%5,%6,%7}, {%8,%9}, {%0,%1,%2,%3};"
        : "+f"(c[0]), "+f"(c[1]), "+f"(c[2]), "+f"(c[3])
        : "r"(a[0]), "r"(a[1]), "r"(a[2]), "r"(a[3]), "r"(b[0]), "r"(b[1]));
}

__device__ __forceinline__ void cp_async16(uint32_t saddr, const void* gptr) {
    asm volatile("cp.async.cg.shared.global [%0], [%1], 16;"
                 :: "r"(saddr), "l"(gptr) : "memory");
}
#define CP_COMMIT() asm volatile("cp.async.commit_group;" ::: "memory")
#define CP_WAIT0()  asm volatile("cp.async.wait_group 0;" ::: "memory")

// Cross-block reduce helper (512 threads, 16 warps)
__device__ __forceinline__ float block_sum(float v, float* wred, float* bcast,
                                           int lane, int wid, int tid) {
    #pragma unroll
    for (int off = 16; off > 0; off >>= 1)
        v += __shfl_xor_sync(0xffffffffu, v, off);
    if (lane == 0) wred[wid] = v;
    __syncthreads();
    if (tid == 0) {
        float tot = 0.0f;
        #pragma unroll
        for (int w = 0; w < 16; w++) tot += wred[w];
        *bcast = tot;
    }
    __syncthreads();
    float r = *bcast;
    __syncthreads();
    return r;
}

// ---------------------------------------------------------------------------
// prep_all: fused independent preprocessing, 256 threads/block.
#define PREP_V_BLOCKS 8192
#define PREP_GRID (69 + PREP_V_BLOCKS)

__global__ __launch_bounds__(256)
void prep_all_kernel(const float* __restrict__ query,
                     const float* __restrict__ values_a,
                     const float* __restrict__ values_b,
                     const unsigned char* __restrict__ mask_raw,
                     const float* __restrict__ Wk_a,
                     const float* __restrict__ Wk_b,
                     const float* __restrict__ Wq_a,
                     const float* __restrict__ Wq_b) {
    int bid = blockIdx.x;
    int tid = threadIdx.x;

    if (bid >= 69) {
        // ---- V -> bf16 ----
        int vb = bid - 69;
        #pragma unroll
        for (int i = 0; i < 8; i++) {
            size_t op = ((size_t)vb * 8 + i) * 256 + tid;
            size_t e = op * 8;
            int head = e >= (size_t)VHALF;
            size_t off = e - (size_t)head * VHALF;
            const float* src = head ? values_b : values_a;
            float4 a = *(const float4*)(src + off);
            float4 c = *(const float4*)(src + off + 4);
            uint4 o;
            o.x = pack_bf2(a.x, a.y); o.y = pack_bf2(a.z, a.w);
            o.z = pack_bf2(c.x, c.y); o.w = pack_bf2(c.z, c.w);
            ((uint4*)g_Vb)[op] = o;
        }
    } else if (bid == 0) {
        __shared__ int c[4];
        if (tid < 4) c[tid] = 0;
        __syncthreads();
        int local[4] = {0, 0, 0, 0};
        for (int i = tid; i < 32768; i += 256)
            if (mask_raw[i]) local[i & 3]++;
        #pragma unroll
        for (int j = 0; j < 4; j++) if (local[j]) atomicAdd(&c[j], local[j]);
        __syncthreads();
        if (tid == 0) {
            int mode;
            if (c[1] > 0)      mode = 0;
            else if (c[0] > 0) mode = 1;
            else               mode = 2;
            g_mask_mode = mode;
        }
    } else if (bid <= 4) {
        int gid = (bid - 1) * 256 + tid;
        int head = gid >> 9;
        int n = gid & 511;
        const float* Wk = head ? Wk_b : Wk_a;
        #pragma unroll 2
        for (int kc = 0; kc < 64; kc++) {
            float x[8];
            #pragma unroll
            for (int j = 0; j < 8; j++)
                x[j] = Wk[(size_t)(kc * 8 + j) * HD + n];
            uint4 o;
            o.x = pack_bf2(x[0], x[1]); o.y = pack_bf2(x[2], x[3]);
            o.z = pack_bf2(x[4], x[5]); o.w = pack_bf2(x[6], x[7]);
            *(uint4*)(&g_Bt[head][n][kc * 8]) = o;
        }
    } else {
        int zb = bid - 5;
        int head = zb >> 5;
        int b    = zb & 31;
        const float* Wq = head ? Wq_b : Wq_a;
        __shared__ float q[HD];
        __shared__ float part[4][HD];
        q[tid] = query[b * HD + tid];
        q[tid + 256] = query[b * HD + tid + 256];
        __syncthreads();
        int kq = tid >> 6;
        int hg = (tid & 63) * 8;
        float acc[8];
        #pragma unroll
        for (int j = 0; j < 8; j++) acc[j] = 0.0f;
        const float* Wbase = Wq + (size_t)(kq * 128) * HD + hg;
        #pragma unroll 2
        for (int k = 0; k < 128; k++) {
            float qk = q[kq * 128 + k];
            float4 w0 = *(const float4*)(Wbase + (size_t)k * HD);
            float4 w1 = *(const float4*)(Wbase + (size_t)k * HD + 4);
            acc[0] = fmaf(qk, w0.x, acc[0]); acc[1] = fmaf(qk, w0.y, acc[1]);
            acc[2] = fmaf(qk, w0.z, acc[2]); acc[3] = fmaf(qk, w0.w, acc[3]);
            acc[4] = fmaf(qk, w1.x, acc[4]); acc[5] = fmaf(qk, w1.y, acc[5]);
            acc[6] = fmaf(qk, w1.z, acc[6]); acc[7] = fmaf(qk, w1.w, acc[7]);
        }
        *(float4*)&part[kq][hg]     = make_float4(acc[0], acc[1], acc[2], acc[3]);
        *(float4*)&part[kq][hg + 4] = make_float4(acc[4], acc[5], acc[6], acc[7]);
        __syncthreads();
        g_pq[head][b][tid] = (part[0][tid] + part[1][tid]) +
                             (part[2][tid] + part[3][tid]);
        int t2 = tid + 256;
        g_pq[head][b][t2] = (part[0][t2] + part[1][t2]) +
                            (part[2][t2] + part[3][t2]);
    }
}

// ---------------------------------------------------------------------------
// Hot kernel: bf16 mma.sync GEMM; A and B both via cp.async (unchanged R9).
#define SMA0 0
#define SMA1 18432
#define SMB0 36864
#define SMB1 55296
#define SM_PS  73728
#define SM_VS  74240
#define SM_RED 74752
#define SM_TOTAL 76800

__global__ __launch_bounds__(256, 2)
void score_mma_kernel(const float* __restrict__ v_a,
                      const float* __restrict__ v_b) {
    int sc = blockIdx.x;
    int nh = blockIdx.y;
    int zb = blockIdx.z;
    int head = zb >> 5;
    int b    = zb & 31;
    const float* vv = head ? v_b : v_a;

    extern __shared__ char smem[];
    uint32_t sb = smem_u32(smem);
    int tid = threadIdx.x, lane = tid & 31, wid = tid >> 5;
    int warp_m = wid & 1, warp_n = wid >> 1;

    float acc[4][4][4];
    #pragma unroll
    for (int mf = 0; mf < 4; mf++)
        #pragma unroll
        for (int nf = 0; nf < 4; nf++)
            #pragma unroll
            for (int r = 0; r < 4; r++) acc[mf][nf][r] = 0.0f;

    const __nv_bfloat16* Asrc = &g_Vb[head][b][sc * 128][0];
    const __nv_bfloat16* Bsrc = &g_Bt[head][nh * 128][0];

    int sr[4], sg[4];
    #pragma unroll
    for (int i = 0; i < 4; i++) {
        int idx = i * 256 + tid;
        sr[i] = idx >> 3;
        sg[i] = idx & 7;
    }

    uint32_t aRow = (uint32_t)(warp_m * 64 + (lane & 15));
    uint32_t aColB = (uint32_t)((lane >> 4) * 16);
    uint32_t bRow = (uint32_t)(warp_n * 32 + (lane & 7) + ((lane >> 4) & 1) * 8);
    uint32_t bColB = (uint32_t)(((lane >> 3) & 1) * 16);

    #pragma unroll
    for (int i = 0; i < 4; i++) {
        cp_async16(sb + SMA0 + sr[i] * 144 + sg[i] * 16,
                   Asrc + (size_t)sr[i] * KD + sg[i] * 8);
        cp_async16(sb + SMB0 + sr[i] * 144 + sg[i] * 16,
                   Bsrc + (size_t)sr[i] * KD + sg[i] * 8);
    }
    CP_COMMIT();
    CP_WAIT0();
    __syncthreads();

    for (int kc = 0; kc < 8; kc++) {
        int cur = kc & 1;
        uint32_t Ab = sb + (cur ? SMA1 : SMA0);
        uint32_t Bb = sb + (cur ? SMB1 : SMB0);
        uint32_t An = sb + (cur ? SMA0 : SMA1);
        uint32_t Bn = sb + (cur ? SMB0 : SMB1);
        if (kc < 7) {
            #pragma unroll
            for (int i = 0; i < 4; i++) {
                cp_async16(An + sr[i] * 144 + sg[i] * 16,
                           Asrc + (size_t)sr[i] * KD + (kc + 1) * 64 + sg[i] * 8);
                cp_async16(Bn + sr[i] * 144 + sg[i] * 16,
                           Bsrc + (size_t)sr[i] * KD + (kc + 1) * 64 + sg[i] * 8);
            }
            CP_COMMIT();
        }
        #pragma unroll
        for (int ks = 0; ks < 4; ks++) {
            uint32_t af[4][4], bf[2][4];
            #pragma unroll
            for (int mf = 0; mf < 4; mf++) {
                uint32_t off = (aRow + mf * 16) * 144 + ks * 32 + aColB;
                ldsm4(af[mf][0], af[mf][1], af[mf][2], af[mf][3], Ab + off);
            }
            #pragma unroll
            for (int p = 0; p < 2; p++) {
                uint32_t off = (bRow + p * 16) * 144 + ks * 32 + bColB;
                ldsm4(bf[p][0], bf[p][1], bf[p][2], bf[p][3], Bb + off);
            }
            #pragma unroll
            for (int mf = 0; mf < 4; mf++)
                #pragma unroll
                for (int p = 0; p < 2; p++) {
                    mma_bf16(acc[mf][2 * p + 0], af[mf], &bf[p][0]);
                    mma_bf16(acc[mf][2 * p + 1], af[mf], &bf[p][2]);
                }
        }
        if (kc < 7) CP_WAIT0();
        __syncthreads();
    }

    float* ps  = (float*)(smem + SM_PS);
    float* vs  = (float*)(smem + SM_VS);
    float* red = (float*)(smem + SM_RED);
    if (tid < 128) {
        ps[tid] = g_pq[head][b][nh * 128 + tid];
        vs[tid] = vv[nh * 128 + tid];
    }
    __syncthreads();

    #pragma unroll
    for (int mf = 0; mf < 4; mf++) {
        float slo = 0.0f, shi = 0.0f;
        #pragma unroll
        for (int nf = 0; nf < 4; nf++) {
            int h = warp_n * 32 + nf * 8 + (lane & 3) * 2;
            slo = fmaf(vs[h],     tanh_fast(acc[mf][nf][0] + ps[h]),     slo);
            slo = fmaf(vs[h + 1], tanh_fast(acc[mf][nf][1] + ps[h + 1]), slo);
            shi = fmaf(vs[h],     tanh_fast(acc[mf][nf][2] + ps[h]),     shi);
            shi = fmaf(vs[h + 1], tanh_fast(acc[mf][nf][3] + ps[h + 1]), shi);
        }
        slo += __shfl_xor_sync(0xffffffffu, slo, 1);
        slo += __shfl_xor_sync(0xffffffffu, slo, 2);
        shi += __shfl_xor_sync(0xffffffffu, shi, 1);
        shi += __shfl_xor_sync(0xffffffffu, shi, 2);
        if ((lane & 3) == 0) {
            int row = warp_m * 64 + mf * 16 + (lane >> 2);
            red[row * 4 + warp_n]       = slo;
            red[(row + 8) * 4 + warp_n] = shi;
        }
    }
    __syncthreads();
    if (tid < 128) {
        float s = (red[tid * 4 + 0] + red[tid * 4 + 1]) +
                  (red[tid * 4 + 2] + red[tid * 4 + 3]);
        g_scp[nh][head][b][sc * 128 + tid] = s;
    }
}

// ---------------------------------------------------------------------------
// Pass 1: register-resident bisect (16 iters; MARGIN covers the slack).
__global__ void spmax_pass1_kernel(const void* __restrict__ ma,
                                   const void* __restrict__ mb) {
    int head = blockIdx.x >> 5;
    int b    = blockIdx.x & 31;
    const void* mp = head ? mb : ma;
    int mode = g_mask_mode;

    __shared__ float wred[16];
    __shared__ float bcast;
    __shared__ int scnt;

    int tid  = threadIdx.x;
    int lane = tid & 31;
    int wid  = tid >> 5;
    if (tid == 0) scnt = 0;
    int i0 = tid * 8;

    float zr[8];
    #pragma unroll
    for (int j = 0; j < 8; j++) zr[j] = 0.0f;
    #pragma unroll
    for (int nh = 0; nh < 4; nh++) {
        const float4* p = (const float4*)&g_scp[nh][head][b][i0];
        float4 a = p[0], c = p[1];
        zr[0] += a.x; zr[1] += a.y; zr[2] += a.z; zr[3] += a.w;
        zr[4] += c.x; zr[5] += c.y; zr[6] += c.z; zr[7] += c.w;
    }
    if (mode == 1) {
        const int4* p = (const int4*)((const int*)mp + b * SS + i0);
        int4 m0 = p[0], m1 = p[1];
        int mm[8] = {m0.x, m0.y, m0.z, m0.w, m1.x, m1.y, m1.z, m1.w};
        #pragma unroll
        for (int j = 0; j < 8; j++) if (!mm[j]) zr[j] = NEGV;
    } else if (mode == 0) {
        const unsigned char* p = (const unsigned char*)mp + b * SS + i0;
        #pragma unroll
        for (int j = 0; j < 8; j++) if (!p[j]) zr[j] = NEGV;
    } else {
        const float4* p = (const float4*)((const float*)mp + b * SS + i0);
        float4 m0 = p[0], m1 = p[1];
        float mm[8] = {m0.x, m0.y, m0.z, m0.w, m1.x, m1.y, m1.z, m1.w};
        #pragma unroll
        for (int j = 0; j < 8; j++) if (mm[j] == 0.0f) zr[j] = NEGV;
    }
    {
        float4* q = (float4*)&g_scores[head][b][i0];
        q[0] = make_float4(zr[0], zr[1], zr[2], zr[3]);
        q[1] = make_float4(zr[4], zr[5], zr[6], zr[7]);
    }

    float lmax = zr[0];
    #pragma unroll
    for (int j = 1; j < 8; j++) lmax = fmaxf(lmax, zr[j]);
    #pragma unroll
    for (int off = 16; off > 0; off >>= 1)
        lmax = fmaxf(lmax, __shfl_xor_sync(0xffffffffu, lmax, off));
    if (lane == 0) wred[wid] = lmax;
    __syncthreads();
    if (tid == 0) {
        float m = wred[0];
        for (int w = 1; w < 16; w++) m = fmaxf(m, wred[w]);
        bcast = m;
    }
    __syncthreads();
    float zmax = bcast;
    __syncthreads();

    float lo = zmax - 1.0f, hi = zmax;
    for (int it = 0; it < 16; it++) {
        float mid = 0.5f * (lo + hi);
        float s = 0.0f;
        #pragma unroll
        for (int j = 0; j < 8; j++) s += fmaxf(zr[j] - mid, 0.0f);
        float tot = block_sum(s, wred, &bcast, lane, wid, tid);
        if (tot >= 1.0f) lo = mid; else hi = mid;
    }
    float tau = 0.5f * (lo + hi);

    float thr = tau - MARGIN;
    #pragma unroll
    for (int j = 0; j < 8; j++) {
        if (zr[j] > thr) {
            int p = atomicAdd(&scnt, 1);
            if (p < MAXCAND) g_cand[head][b][p] = i0 + j;
        }
    }
    __syncthreads();
    if (tid == 0) g_ccnt[head][b] = scnt < MAXCAND ? scnt : MAXCAND;
}

// ---------------------------------------------------------------------------
// Refine v4: v1 structure + Wk streamed through double-buffered smem
// (cp.async), so the 512-k loop reads only LDS (no exposed L2 latency).
// Grid 256 = (head, b, quad), 256 threads, batch 8 candidates.
// Dynamic smem: WK0 32KB | WK1 32KB | VROW 16KB | RED 256B
#define RSM_WK0  0
#define RSM_WK1  32768
#define RSM_VROW 65536
#define RSM_RED  (RSM_VROW + 16384)
#define RSM_TOTAL (RSM_RED + 256)

__global__ __launch_bounds__(256, 2)
void refine_kernel(const float* __restrict__ values_a,
                   const float* __restrict__ values_b,
                   const float* __restrict__ Wk_a,
                   const float* __restrict__ Wk_b,
                   const float* __restrict__ v_a,
                   const float* __restrict__ v_b) {
    int head = blockIdx.x >> 7;
    int b    = (blockIdx.x >> 2) & 31;
    int quad = blockIdx.x & 3;
    const float* V  = head ? values_b : values_a;
    const float* Wk = head ? Wk_b : Wk_a;
    const float* vv = head ? v_b : v_a;

    extern __shared__ char rsm[];
    float* vrow = (float*)(rsm + RSM_VROW);   // [8][512]
    float* red  = (float*)(rsm + RSM_RED);    // [8][8]
    uint32_t sbase = smem_u32(rsm);

    int t = threadIdx.x, lane = t & 31, wid = t >> 5;
    float pq0 = g_pq[head][b][t], pq1 = g_pq[head][b][t + 256];
    float vv0 = vv[t], vv1 = vv[t + 256];

    // per-thread Wk staging indices: 8 float4 per 16-row chunk
    // chunk = 16 rows x 512 floats = 2048 float4; idx = i*256 + t
    int cnt = g_ccnt[head][b];
    for (int base = quad; base < cnt; base += 32) {
        // stage 8 candidate rows into smem
        #pragma unroll
        for (int g = 0; g < 8; g++) {
            int ci = base + g * 4;
            if (ci < cnt) {
                int row = g_cand[head][b][ci];
                const float* src = V + ((size_t)b * SS + row) * KD;
                vrow[g * 512 + t]       = src[t];
                vrow[g * 512 + t + 256] = src[t + 256];
            } else {
                vrow[g * 512 + t]       = 0.0f;
                vrow[g * 512 + t + 256] = 0.0f;
            }
        }

        // prologue: stage Wk chunk 0 (rows 0..15)
        #pragma unroll
        for (int i = 0; i < 8; i++) {
            int idx = i * 256 + t;
            int r = idx >> 7;                 // row in chunk (128 f4/row)
            int c4 = idx & 127;               // float4 within row
            cp_async16(sbase + RSM_WK0 + r * 2048 + c4 * 16,
                       Wk + (size_t)r * HD + c4 * 4);
        }
        CP_COMMIT();
        CP_WAIT0();
        __syncthreads();

        float a0[8], a1[8];
        #pragma unroll
        for (int g = 0; g < 8; g++) { a0[g] = 0.0f; a1[g] = 0.0f; }

        for (int kc = 0; kc < 32; kc++) {
            int cur = kc & 1;
            const float* wk = (const float*)(rsm + (cur ? RSM_WK1 : RSM_WK0));
            uint32_t nxt = sbase + (cur ? RSM_WK0 : RSM_WK1);
            // prefetch next Wk chunk (overlaps compute)
            if (kc < 31) {
                const float* Wsrc = Wk + (size_t)(kc + 1) * 16 * HD;
                #pragma unroll
                for (int i = 0; i < 8; i++) {
                    int idx = i * 256 + t;
                    int r = idx >> 7;
                    int c4 = idx & 127;
                    cp_async16(nxt + r * 2048 + c4 * 16,
                               Wsrc + (size_t)r * HD + c4 * 4);
                }
                CP_COMMIT();
            }
            // compute 16 k from current chunk (all LDS)
            int kg = kc * 16;
            #pragma unroll
            for (int k = 0; k < 16; k++) {
                float w0 = wk[k * 512 + t];
                float w1 = wk[k * 512 + t + 256];
                #pragma unroll
                for (int g = 0; g < 8; g++) {
                    float x = vrow[g * 512 + kg + k];
                    a0[g] = fmaf(x, w0, a0[g]);
                    a1[g] = fmaf(x, w1, a1[g]);
                }
            }
            if (kc < 31) CP_WAIT0();
            __syncthreads();
        }

        #pragma unroll
        for (int g = 0; g < 8; g++) {
            float s = vv0 * tanh_fast(pq0 + a0[g]) + vv1 * tanh_fast(pq1 + a1[g]);
            #pragma unroll
            for (int off = 16; off > 0; off >>= 1)
                s += __shfl_xor_sync(0xffffffffu, s, off);
            if (lane == 0) red[g * 8 + wid] = s;
        }
        __syncthreads();
        if (t < 8) {
            int ci = base + t * 4;
            if (ci < cnt) {
                float s = 0.0f;
                #pragma unroll
                for (int w = 0; w < 8; w++) s += red[t * 8 + w];
                g_scores[head][b][g_cand[head][b][ci]] = s;
            }
        }
        __syncthreads();
    }
}

// ---------------------------------------------------------------------------
// Pass 2: register-resident bisect (30 iters) + compact context.
__global__ void sparsemax_kernel(const float* __restrict__ values_a,
                                 const float* __restrict__ values_b,
                                 float* __restrict__ out) {
    int head = blockIdx.x >> 5;
    int b    = blockIdx.x & 31;
    const float* V = head ? values_b : values_a;

    __shared__ float wred[16];
    __shared__ float bcast;
    __shared__ int   sidx[MAXCAND];
    __shared__ float sal[MAXCAND];
    __shared__ int   snum;

    int tid  = threadIdx.x;
    int lane = tid & 31;
    int wid  = tid >> 5;
    if (tid == 0) snum = 0;
    int i0 = tid * 8;

    float zr[8];
    {
        const float4* p = (const float4*)&g_scores[head][b][i0];
        float4 a = p[0], c = p[1];
        zr[0] = a.x; zr[1] = a.y; zr[2] = a.z; zr[3] = a.w;
        zr[4] = c.x; zr[5] = c.y; zr[6] = c.z; zr[7] = c.w;
    }

    float lmax = zr[0];
    #pragma unroll
    for (int j = 1; j < 8; j++) lmax = fmaxf(lmax, zr[j]);
    #pragma unroll
    for (int off = 16; off > 0; off >>= 1)
        lmax = fmaxf(lmax, __shfl_xor_sync(0xffffffffu, lmax, off));
    if (lane == 0) wred[wid] = lmax;
    __syncthreads();
    if (tid == 0) {
        float m = wred[0];
        for (int w = 1; w < 16; w++) m = fmaxf(m, wred[w]);
        bcast = m;
    }
    __syncthreads();
    float zmax = bcast;
    __syncthreads();

    float lo = zmax - 1.0f, hi = zmax;
    for (int it = 0; it < 30; it++) {
        float mid = 0.5f * (lo + hi);
        float s = 0.0f;
        #pragma unroll
        for (int j = 0; j < 8; j++) s += fmaxf(zr[j] - mid, 0.0f);
        float tot = block_sum(s, wred, &bcast, lane, wid, tid);
        if (tot >= 1.0f) lo = mid; else hi = mid;
    }
    float tau = 0.5f * (lo + hi);

    float* alout = out + OUT_AL + (size_t)head * BB * SS + (size_t)b * SS;
    float al[8];
    #pragma unroll
    for (int j = 0; j < 8; j++) al[j] = fmaxf(zr[j] - tau, 0.0f);
    {
        float4* q = (float4*)(alout + i0);
        q[0] = make_float4(al[0], al[1], al[2], al[3]);
        q[1] = make_float4(al[4], al[5], al[6], al[7]);
    }
    #pragma unroll
    for (int j = 0; j < 8; j++) {
        if (al[j] > 0.0f) {
            int p = atomicAdd(&snum, 1);
            if (p < MAXCAND) { sidx[p] = i0 + j; sal[p] = al[j]; }
        }
    }
    __syncthreads();

    const float* Vb = V + (size_t)b * SS * KD;
    float ctx = 0.0f;
    int ns = snum;
    if (ns <= MAXCAND) {
        for (int j = 0; j < ns; j++)
            ctx = fmaf(sal[j], Vb[(size_t)sidx[j] * KD + tid], ctx);
    } else {
        for (int s = 0; s < SS; s++) {
            float a = alout[s];
            if (a > 0.0f) ctx = fmaf(a, Vb[(size_t)s * KD + tid], ctx);
        }
    }
    g_ctx[head][b][tid] = ctx;
}

// ---------------------------------------------------------------------------
// Merge: gate softmax + candidates + blend. (h-quad x k-quarter) layout.
__global__ void merge_kernel(const float* __restrict__ query,
                             const float* __restrict__ Wg,
                             const float* __restrict__ bg,
                             const float* __restrict__ Wu_a,
                             const float* __restrict__ bu_a,
                             const float* __restrict__ Wu_b,
                             const float* __restrict__ bu_b,
                             float* __restrict__ out) {
    int b = blockIdx.x;
    int t = threadIdx.x;
    int lane = t & 31, wid = t >> 5;
    __shared__ float qv[HD], ca[KD], cb[KD];
    __shared__ float part_a[4][HD], part_b[4][HD];
    __shared__ float red0[16], red1[16];
    __shared__ float w01[2];

    qv[t] = query[b * HD + t];
    ca[t] = g_ctx[0][b][t];
    cb[t] = g_ctx[1][b][t];
    __syncthreads();

    float p0 = 0.0f, p1 = 0.0f;
    {
        float x = qv[t];
        p0 = fmaf(x, Wg[t * 2 + 0], p0);  p1 = fmaf(x, Wg[t * 2 + 1], p1);
        x = ca[t];
        p0 = fmaf(x, Wg[(512 + t) * 2 + 0], p0);  p1 = fmaf(x, Wg[(512 + t) * 2 + 1], p1);
        x = cb[t];
        p0 = fmaf(x, Wg[(1024 + t) * 2 + 0], p0); p1 = fmaf(x, Wg[(1024 + t) * 2 + 1], p1);
    }
    #pragma unroll
    for (int off = 16; off > 0; off >>= 1) {
        p0 += __shfl_xor_sync(0xffffffffu, p0, off);
        p1 += __shfl_xor_sync(0xffffffffu, p1, off);
    }
    if (lane == 0) { red0[wid] = p0; red1[wid] = p1; }
    __syncthreads();
    if (t == 0) {
        float g0 = bg[0], g1 = bg[1];
        for (int w = 0; w < 16; w++) { g0 += red0[w]; g1 += red1[w]; }
        float m = fmaxf(g0, g1);
        float e0 = expf(g0 - m), e1 = expf(g1 - m);
        float inv = 1.0f / (e0 + e1);
        w01[0] = e0 * inv;
        w01[1] = e1 * inv;
    }
    __syncthreads();

    int hq = (t & 127) * 4;
    int kq = t >> 7;
    const float* xa_seg = (kq < 2) ? (qv + kq * 256) : (ca + (kq - 2) * 256);
    const float* xb_seg = (kq < 2) ? (qv + kq * 256) : (cb + (kq - 2) * 256);
    const float* Wua = Wu_a + (size_t)(kq * 256) * HD + hq;
    const float* Wub = Wu_b + (size_t)(kq * 256) * HD + hq;
    float4 aa = make_float4(0.f, 0.f, 0.f, 0.f);
    float4 ab = make_float4(0.f, 0.f, 0.f, 0.f);
    #pragma unroll 2
    for (int i = 0; i < 256; i++) {
        float xa = xa_seg[i], xb = xb_seg[i];
        float4 wa = *(const float4*)(Wua + (size_t)i * HD);
        float4 wb = *(const float4*)(Wub + (size_t)i * HD);
        aa.x = fmaf(xa, wa.x, aa.x); aa.y = fmaf(xa, wa.y, aa.y);
        aa.z = fmaf(xa, wa.z, aa.z); aa.w = fmaf(xa, wa.w, aa.w);
        ab.x = fmaf(xb, wb.x, ab.x); ab.y = fmaf(xb, wb.y, ab.y);
        ab.z = fmaf(xb, wb.z, ab.z); ab.w = fmaf(xb, wb.w, ab.w);
    }
    *(float4*)&part_a[kq][hq] = aa;
    *(float4*)&part_b[kq][hq] = ab;
    __syncthreads();

    float w0 = w01[0], w1 = w01[1];
    float sa = bu_a[t] + (part_a[0][t] + part_a[1][t]) + (part_a[2][t] + part_a[3][t]);
    float sb = bu_b[t] + (part_b[0][t] + part_b[1][t]) + (part_b[2][t] + part_b[3][t]);
    out[OUT_ATT + b * HD + t] = w0 * tanhf(sa) + w1 * tanhf(sb);
}

// ---------------------------------------------------------------------------
extern "C" void kernel_launch(void* const* d_in, const int* in_sizes, int n_in,
                              void* d_out, int out_size) {
    const float* query    = (const float*)d_in[0];
    const float* values_a = (const float*)d_in[1];
    const float* values_b = (const float*)d_in[2];
    const void*  mask_a   = d_in[3];
    const void*  mask_b   = d_in[4];
    const float* Wk_a = (const float*)d_in[5];
    const float* Wq_a = (const float*)d_in[6];
    const float* v_a  = (const float*)d_in[7];
    const float* Wk_b = (const float*)d_in[8];
    const float* Wq_b = (const float*)d_in[9];
    const float* v_b  = (const float*)d_in[10];
    const float* Wg   = (const float*)d_in[11];
    const float* bg   = (const float*)d_in[12];
    const float* Wu_a = (const float*)d_in[13];
    const float* bu_a = (const float*)d_in[14];
    const float* Wu_b = (const float*)d_in[15];
    const float* bu_b = (const float*)d_in[16];
    float* out = (float*)d_out;

    cudaFuncSetAttribute(score_mma_kernel,
                         cudaFuncAttributeMaxDynamicSharedMemorySize, SM_TOTAL);
    cudaFuncSetAttribute(refine_kernel,
                         cudaFuncAttributeMaxDynamicSharedMemorySize, RSM_TOTAL);

    prep_all_kernel<<<PREP_GRID, 256>>>(query, values_a, values_b,
                                        (const unsigned char*)mask_a,
                                        Wk_a, Wk_b, Wq_a, Wq_b);
    dim3 g1(32, 4, 64);
    score_mma_kernel<<<g1, 256, SM_TOTAL>>>(v_a, v_b);
    spmax_pass1_kernel<<<64, 512>>>(mask_a, mask_b);
    refine_kernel<<<256, 256, RSM_TOTAL>>>(values_a, values_b, Wk_a, Wk_b,
                                           v_a, v_b);
    sparsemax_kernel<<<64, 512>>>(values_a, values_b, out);
    merge_kernel<<<32, 512>>>(query, Wg, bg, Wu_a, bu_a, Wu_b, bu_b, out);
}

// round 13
// speedup vs baseline: 1.1403x; 1.0001x over previous
#include <cuda_runtime.h>
#include <cuda_bf16.h>
#include <math.h>
#include <stdint.h>

// Problem constants
#define BB 32
#define SS 4096
#define KD 512
#define HD 512
#define NEGV (-1e9f)
#define MARGIN 0.125f
#define MAXCAND 512
#define VHALF (BB*SS*KD)     // elements per head in V

// Output layout: [att_vector (32*512) | al_a (32*4096) | al_b (32*4096)]
#define OUT_ATT 0
#define OUT_AL  (BB*HD)

// Scratch (device globals; no allocations allowed)
__device__ float g_pq[2][BB][HD];
__device__ float g_scp[4][2][BB][SS];     // per-nh partial approx scores
__device__ float g_scores[2][BB][SS];     // masked -> refined scores
__device__ float g_ctx[2][BB][KD];
__device__ int   g_mask_mode;
__device__ __nv_bfloat16 g_Bt[2][HD][KD]; // transposed bf16 Wk: g_Bt[h][n][k]
__device__ __nv_bfloat16 g_Vb[2][BB][SS][KD]; // bf16 copy of values (256 MB)
__device__ int   g_cand[2][BB][MAXCAND];
__device__ int   g_ccnt[2][BB];

// ---------------------------------------------------------------------------
__device__ __forceinline__ float tanh_fast(float x) {
    float cx = fminf(fmaxf(x, -15.0f), 15.0f);
    float e = __expf(2.0f * cx);
    return __fdividef(e - 1.0f, e + 1.0f);
}

__device__ __forceinline__ uint32_t smem_u32(const void* p) {
    uint32_t a;
    asm("{ .reg .u64 t; cvta.to.shared.u64 t, %1; cvt.u32.u64 %0, t; }"
        : "=r"(a) : "l"(p));
    return a;
}

__device__ __forceinline__ uint32_t pack_bf2(float x0, float x1) {
    uint32_t d;
    asm("cvt.rn.satfinite.bf16x2.f32 %0, %1, %2;" : "=r"(d) : "f"(x1), "f"(x0));
    return d;
}

__device__ __forceinline__ void ldsm4(uint32_t& r0, uint32_t& r1,
                                      uint32_t& r2, uint32_t& r3, uint32_t a) {
    asm volatile("ldmatrix.sync.aligned.m8n8.x4.shared.b16 {%0,%1,%2,%3}, [%4];"
                 : "=r"(r0), "=r"(r1), "=r"(r2), "=r"(r3) : "r"(a));
}

__device__ __forceinline__ void mma_bf16(float* c, const uint32_t* a,
                                         const uint32_t* b) {
    asm volatile(
        "mma.sync.aligned.m16n8k16.row.col.f32.bf16.bf16.f32 "
        "{%0,%1,%2,%3}, {%4,%5,%6,%7}, {%8,%9}, {%0,%1,%2,%3};"
        : "+f"(c[0]), "+f"(c[1]), "+f"(c[2]), "+f"(c[3])
        : "r"(a[0]), "r"(a[1]), "r"(a[2]), "r"(a[3]), "r"(b[0]), "r"(b[1]));
}

__device__ __forceinline__ void cp_async16(uint32_t saddr, const void* gptr) {
    asm volatile("cp.async.cg.shared.global [%0], [%1], 16;"
                 :: "r"(saddr), "l"(gptr) : "memory");
}
#define CP_COMMIT() asm volatile("cp.async.commit_group;" ::: "memory")
#define CP_WAIT0()  asm volatile("cp.async.wait_group 0;" ::: "memory")

// Cross-block reduce helper (512 threads, 16 warps)
__device__ __forceinline__ float block_sum(float v, float* wred, float* bcast,
                                           int lane, int wid, int tid) {
    #pragma unroll
    for (int off = 16; off > 0; off >>= 1)
        v += __shfl_xor_sync(0xffffffffu, v, off);
    if (lane == 0) wred[wid] = v;
    __syncthreads();
    if (tid == 0) {
        float tot = 0.0f;
        #pragma unroll
        for (int w = 0; w < 16; w++) tot += wred[w];
        *bcast = tot;
    }
    __syncthreads();
    float r = *bcast;
    __syncthreads();
    return r;
}

// ---------------------------------------------------------------------------
// prep_all: fused independent preprocessing, 256 threads/block.
#define PREP_V_BLOCKS 8192
#define PREP_GRID (69 + PREP_V_BLOCKS)

__global__ __launch_bounds__(256)
void prep_all_kernel(const float* __restrict__ query,
                     const float* __restrict__ values_a,
                     const float* __restrict__ values_b,
                     const unsigned char* __restrict__ mask_raw,
                     const float* __restrict__ Wk_a,
                     const float* __restrict__ Wk_b,
                     const float* __restrict__ Wq_a,
                     const float* __restrict__ Wq_b) {
    int bid = blockIdx.x;
    int tid = threadIdx.x;

    if (bid >= 69) {
        // ---- V -> bf16 ----
        int vb = bid - 69;
        #pragma unroll
        for (int i = 0; i < 8; i++) {
            size_t op = ((size_t)vb * 8 + i) * 256 + tid;
            size_t e = op * 8;
            int head = e >= (size_t)VHALF;
            size_t off = e - (size_t)head * VHALF;
            const float* src = head ? values_b : values_a;
            float4 a = *(const float4*)(src + off);
            float4 c = *(const float4*)(src + off + 4);
            uint4 o;
            o.x = pack_bf2(a.x, a.y); o.y = pack_bf2(a.z, a.w);
            o.z = pack_bf2(c.x, c.y); o.w = pack_bf2(c.z, c.w);
            ((uint4*)g_Vb)[op] = o;
        }
    } else if (bid == 0) {
        __shared__ int c[4];
        if (tid < 4) c[tid] = 0;
        __syncthreads();
        int local[4] = {0, 0, 0, 0};
        for (int i = tid; i < 32768; i += 256)
            if (mask_raw[i]) local[i & 3]++;
        #pragma unroll
        for (int j = 0; j < 4; j++) if (local[j]) atomicAdd(&c[j], local[j]);
        __syncthreads();
        if (tid == 0) {
            int mode;
            if (c[1] > 0)      mode = 0;
            else if (c[0] > 0) mode = 1;
            else               mode = 2;
            g_mask_mode = mode;
        }
    } else if (bid <= 4) {
        int gid = (bid - 1) * 256 + tid;
        int head = gid >> 9;
        int n = gid & 511;
        const float* Wk = head ? Wk_b : Wk_a;
        #pragma unroll 2
        for (int kc = 0; kc < 64; kc++) {
            float x[8];
            #pragma unroll
            for (int j = 0; j < 8; j++)
                x[j] = Wk[(size_t)(kc * 8 + j) * HD + n];
            uint4 o;
            o.x = pack_bf2(x[0], x[1]); o.y = pack_bf2(x[2], x[3]);
            o.z = pack_bf2(x[4], x[5]); o.w = pack_bf2(x[6], x[7]);
            *(uint4*)(&g_Bt[head][n][kc * 8]) = o;
        }
    } else {
        int zb = bid - 5;
        int head = zb >> 5;
        int b    = zb & 31;
        const float* Wq = head ? Wq_b : Wq_a;
        __shared__ float q[HD];
        __shared__ float part[4][HD];
        q[tid] = query[b * HD + tid];
        q[tid + 256] = query[b * HD + tid + 256];
        __syncthreads();
        int kq = tid >> 6;
        int hg = (tid & 63) * 8;
        float acc[8];
        #pragma unroll
        for (int j = 0; j < 8; j++) acc[j] = 0.0f;
        const float* Wbase = Wq + (size_t)(kq * 128) * HD + hg;
        #pragma unroll 2
        for (int k = 0; k < 128; k++) {
            float qk = q[kq * 128 + k];
            float4 w0 = *(const float4*)(Wbase + (size_t)k * HD);
            float4 w1 = *(const float4*)(Wbase + (size_t)k * HD + 4);
            acc[0] = fmaf(qk, w0.x, acc[0]); acc[1] = fmaf(qk, w0.y, acc[1]);
            acc[2] = fmaf(qk, w0.z, acc[2]); acc[3] = fmaf(qk, w0.w, acc[3]);
            acc[4] = fmaf(qk, w1.x, acc[4]); acc[5] = fmaf(qk, w1.y, acc[5]);
            acc[6] = fmaf(qk, w1.z, acc[6]); acc[7] = fmaf(qk, w1.w, acc[7]);
        }
        *(float4*)&part[kq][hg]     = make_float4(acc[0], acc[1], acc[2], acc[3]);
        *(float4*)&part[kq][hg + 4] = make_float4(acc[4], acc[5], acc[6], acc[7]);
        __syncthreads();
        g_pq[head][b][tid] = (part[0][tid] + part[1][tid]) +
                             (part[2][tid] + part[3][tid]);
        int t2 = tid + 256;
        g_pq[head][b][t2] = (part[0][t2] + part[1][t2]) +
                            (part[2][t2] + part[3][t2]);
    }
}

// ---------------------------------------------------------------------------
// Hot kernel: bf16 mma.sync GEMM; A and B via cp.async.
// Grid (nh=4, sc=32, zb=64): nh fastest so the 4 CTAs sharing an A tile are
// adjacent in launch order -> A served from L2 instead of 4x DRAM.
#define SMA0 0
#define SMA1 18432
#define SMB0 36864
#define SMB1 55296
#define SM_PS  73728
#define SM_VS  74240
#define SM_RED 74752
#define SM_TOTAL 76800

__global__ __launch_bounds__(256, 2)
void score_mma_kernel(const float* __restrict__ v_a,
                      const float* __restrict__ v_b) {
    int nh = blockIdx.x;          // fastest: A-tile siblings adjacent
    int sc = blockIdx.y;
    int zb = blockIdx.z;
    int head = zb >> 5;
    int b    = zb & 31;
    const float* vv = head ? v_b : v_a;

    extern __shared__ char smem[];
    uint32_t sb = smem_u32(smem);
    int tid = threadIdx.x, lane = tid & 31, wid = tid >> 5;
    int warp_m = wid & 1, warp_n = wid >> 1;

    float acc[4][4][4];
    #pragma unroll
    for (int mf = 0; mf < 4; mf++)
        #pragma unroll
        for (int nf = 0; nf < 4; nf++)
            #pragma unroll
            for (int r = 0; r < 4; r++) acc[mf][nf][r] = 0.0f;

    const __nv_bfloat16* Asrc = &g_Vb[head][b][sc * 128][0];
    const __nv_bfloat16* Bsrc = &g_Bt[head][nh * 128][0];

    int sr[4], sg[4];
    #pragma unroll
    for (int i = 0; i < 4; i++) {
        int idx = i * 256 + tid;
        sr[i] = idx >> 3;
        sg[i] = idx & 7;
    }

    uint32_t aRow = (uint32_t)(warp_m * 64 + (lane & 15));
    uint32_t aColB = (uint32_t)((lane >> 4) * 16);
    uint32_t bRow = (uint32_t)(warp_n * 32 + (lane & 7) + ((lane >> 4) & 1) * 8);
    uint32_t bColB = (uint32_t)(((lane >> 3) & 1) * 16);

    #pragma unroll
    for (int i = 0; i < 4; i++) {
        cp_async16(sb + SMA0 + sr[i] * 144 + sg[i] * 16,
                   Asrc + (size_t)sr[i] * KD + sg[i] * 8);
        cp_async16(sb + SMB0 + sr[i] * 144 + sg[i] * 16,
                   Bsrc + (size_t)sr[i] * KD + sg[i] * 8);
    }
    CP_COMMIT();
    CP_WAIT0();
    __syncthreads();

    for (int kc = 0; kc < 8; kc++) {
        int cur = kc & 1;
        uint32_t Ab = sb + (cur ? SMA1 : SMA0);
        uint32_t Bb = sb + (cur ? SMB1 : SMB0);
        uint32_t An = sb + (cur ? SMA0 : SMA1);
        uint32_t Bn = sb + (cur ? SMB0 : SMB1);
        if (kc < 7) {
            #pragma unroll
            for (int i = 0; i < 4; i++) {
                cp_async16(An + sr[i] * 144 + sg[i] * 16,
                           Asrc + (size_t)sr[i] * KD + (kc + 1) * 64 + sg[i] * 8);
                cp_async16(Bn + sr[i] * 144 + sg[i] * 16,
                           Bsrc + (size_t)sr[i] * KD + (kc + 1) * 64 + sg[i] * 8);
            }
            CP_COMMIT();
        }
        #pragma unroll
        for (int ks = 0; ks < 4; ks++) {
            uint32_t af[4][4], bf[2][4];
            #pragma unroll
            for (int mf = 0; mf < 4; mf++) {
                uint32_t off = (aRow + mf * 16) * 144 + ks * 32 + aColB;
                ldsm4(af[mf][0], af[mf][1], af[mf][2], af[mf][3], Ab + off);
            }
            #pragma unroll
            for (int p = 0; p < 2; p++) {
                uint32_t off = (bRow + p * 16) * 144 + ks * 32 + bColB;
                ldsm4(bf[p][0], bf[p][1], bf[p][2], bf[p][3], Bb + off);
            }
            #pragma unroll
            for (int mf = 0; mf < 4; mf++)
                #pragma unroll
                for (int p = 0; p < 2; p++) {
                    mma_bf16(acc[mf][2 * p + 0], af[mf], &bf[p][0]);
                    mma_bf16(acc[mf][2 * p + 1], af[mf], &bf[p][2]);
                }
        }
        if (kc < 7) CP_WAIT0();
        __syncthreads();
    }

    float* ps  = (float*)(smem + SM_PS);
    float* vs  = (float*)(smem + SM_VS);
    float* red = (float*)(smem + SM_RED);
    if (tid < 128) {
        ps[tid] = g_pq[head][b][nh * 128 + tid];
        vs[tid] = vv[nh * 128 + tid];
    }
    __syncthreads();

    #pragma unroll
    for (int mf = 0; mf < 4; mf++) {
        float slo = 0.0f, shi = 0.0f;
        #pragma unroll
        for (int nf = 0; nf < 4; nf++) {
            int h = warp_n * 32 + nf * 8 + (lane & 3) * 2;
            slo = fmaf(vs[h],     tanh_fast(acc[mf][nf][0] + ps[h]),     slo);
            slo = fmaf(vs[h + 1], tanh_fast(acc[mf][nf][1] + ps[h + 1]), slo);
            shi = fmaf(vs[h],     tanh_fast(acc[mf][nf][2] + ps[h]),     shi);
            shi = fmaf(vs[h + 1], tanh_fast(acc[mf][nf][3] + ps[h + 1]), shi);
        }
        slo += __shfl_xor_sync(0xffffffffu, slo, 1);
        slo += __shfl_xor_sync(0xffffffffu, slo, 2);
        shi += __shfl_xor_sync(0xffffffffu, shi, 1);
        shi += __shfl_xor_sync(0xffffffffu, shi, 2);
        if ((lane & 3) == 0) {
            int row = warp_m * 64 + mf * 16 + (lane >> 2);
            red[row * 4 + warp_n]       = slo;
            red[(row + 8) * 4 + warp_n] = shi;
        }
    }
    __syncthreads();
    if (tid < 128) {
        float s = (red[tid * 4 + 0] + red[tid * 4 + 1]) +
                  (red[tid * 4 + 2] + red[tid * 4 + 3]);
        g_scp[nh][head][b][sc * 128 + tid] = s;
    }
}

// ---------------------------------------------------------------------------
// Pass 1: register-resident bisect (16 iters; MARGIN covers the slack).
__global__ void spmax_pass1_kernel(const void* __restrict__ ma,
                                   const void* __restrict__ mb) {
    int head = blockIdx.x >> 5;
    int b    = blockIdx.x & 31;
    const void* mp = head ? mb : ma;
    int mode = g_mask_mode;

    __shared__ float wred[16];
    __shared__ float bcast;
    __shared__ int scnt;

    int tid  = threadIdx.x;
    int lane = tid & 31;
    int wid  = tid >> 5;
    if (tid == 0) scnt = 0;
    int i0 = tid * 8;

    float zr[8];
    #pragma unroll
    for (int j = 0; j < 8; j++) zr[j] = 0.0f;
    #pragma unroll
    for (int nh = 0; nh < 4; nh++) {
        const float4* p = (const float4*)&g_scp[nh][head][b][i0];
        float4 a = p[0], c = p[1];
        zr[0] += a.x; zr[1] += a.y; zr[2] += a.z; zr[3] += a.w;
        zr[4] += c.x; zr[5] += c.y; zr[6] += c.z; zr[7] += c.w;
    }
    if (mode == 1) {
        const int4* p = (const int4*)((const int*)mp + b * SS + i0);
        int4 m0 = p[0], m1 = p[1];
        int mm[8] = {m0.x, m0.y, m0.z, m0.w, m1.x, m1.y, m1.z, m1.w};
        #pragma unroll
        for (int j = 0; j < 8; j++) if (!mm[j]) zr[j] = NEGV;
    } else if (mode == 0) {
        const unsigned char* p = (const unsigned char*)mp + b * SS + i0;
        #pragma unroll
        for (int j = 0; j < 8; j++) if (!p[j]) zr[j] = NEGV;
    } else {
        const float4* p = (const float4*)((const float*)mp + b * SS + i0);
        float4 m0 = p[0], m1 = p[1];
        float mm[8] = {m0.x, m0.y, m0.z, m0.w, m1.x, m1.y, m1.z, m1.w};
        #pragma unroll
        for (int j = 0; j < 8; j++) if (mm[j] == 0.0f) zr[j] = NEGV;
    }
    {
        float4* q = (float4*)&g_scores[head][b][i0];
        q[0] = make_float4(zr[0], zr[1], zr[2], zr[3]);
        q[1] = make_float4(zr[4], zr[5], zr[6], zr[7]);
    }

    float lmax = zr[0];
    #pragma unroll
    for (int j = 1; j < 8; j++) lmax = fmaxf(lmax, zr[j]);
    #pragma unroll
    for (int off = 16; off > 0; off >>= 1)
        lmax = fmaxf(lmax, __shfl_xor_sync(0xffffffffu, lmax, off));
    if (lane == 0) wred[wid] = lmax;
    __syncthreads();
    if (tid == 0) {
        float m = wred[0];
        for (int w = 1; w < 16; w++) m = fmaxf(m, wred[w]);
        bcast = m;
    }
    __syncthreads();
    float zmax = bcast;
    __syncthreads();

    float lo = zmax - 1.0f, hi = zmax;
    for (int it = 0; it < 16; it++) {
        float mid = 0.5f * (lo + hi);
        float s = 0.0f;
        #pragma unroll
        for (int j = 0; j < 8; j++) s += fmaxf(zr[j] - mid, 0.0f);
        float tot = block_sum(s, wred, &bcast, lane, wid, tid);
        if (tot >= 1.0f) lo = mid; else hi = mid;
    }
    float tau = 0.5f * (lo + hi);

    float thr = tau - MARGIN;
    #pragma unroll
    for (int j = 0; j < 8; j++) {
        if (zr[j] > thr) {
            int p = atomicAdd(&scnt, 1);
            if (p < MAXCAND) g_cand[head][b][p] = i0 + j;
        }
    }
    __syncthreads();
    if (tid == 0) g_ccnt[head][b] = scnt < MAXCAND ? scnt : MAXCAND;
}

// ---------------------------------------------------------------------------
// Refine v4: Wk streamed through double-buffered smem (cp.async).
#define RSM_WK0  0
#define RSM_WK1  32768
#define RSM_VROW 65536
#define RSM_RED  (RSM_VROW + 16384)
#define RSM_TOTAL (RSM_RED + 256)

__global__ __launch_bounds__(256, 2)
void refine_kernel(const float* __restrict__ values_a,
                   const float* __restrict__ values_b,
                   const float* __restrict__ Wk_a,
                   const float* __restrict__ Wk_b,
                   const float* __restrict__ v_a,
                   const float* __restrict__ v_b) {
    int head = blockIdx.x >> 7;
    int b    = (blockIdx.x >> 2) & 31;
    int quad = blockIdx.x & 3;
    const float* V  = head ? values_b : values_a;
    const float* Wk = head ? Wk_b : Wk_a;
    const float* vv = head ? v_b : v_a;

    extern __shared__ char rsm[];
    float* vrow = (float*)(rsm + RSM_VROW);   // [8][512]
    float* red  = (float*)(rsm + RSM_RED);    // [8][8]
    uint32_t sbase = smem_u32(rsm);

    int t = threadIdx.x, lane = t & 31, wid = t >> 5;
    float pq0 = g_pq[head][b][t], pq1 = g_pq[head][b][t + 256];
    float vv0 = vv[t], vv1 = vv[t + 256];

    int cnt = g_ccnt[head][b];
    for (int base = quad; base < cnt; base += 32) {
        #pragma unroll
        for (int g = 0; g < 8; g++) {
            int ci = base + g * 4;
            if (ci < cnt) {
                int row = g_cand[head][b][ci];
                const float* src = V + ((size_t)b * SS + row) * KD;
                vrow[g * 512 + t]       = src[t];
                vrow[g * 512 + t + 256] = src[t + 256];
            } else {
                vrow[g * 512 + t]       = 0.0f;
                vrow[g * 512 + t + 256] = 0.0f;
            }
        }

        #pragma unroll
        for (int i = 0; i < 8; i++) {
            int idx = i * 256 + t;
            int r = idx >> 7;
            int c4 = idx & 127;
            cp_async16(sbase + RSM_WK0 + r * 2048 + c4 * 16,
                       Wk + (size_t)r * HD + c4 * 4);
        }
        CP_COMMIT();
        CP_WAIT0();
        __syncthreads();

        float a0[8], a1[8];
        #pragma unroll
        for (int g = 0; g < 8; g++) { a0[g] = 0.0f; a1[g] = 0.0f; }

        for (int kc = 0; kc < 32; kc++) {
            int cur = kc & 1;
            const float* wk = (const float*)(rsm + (cur ? RSM_WK1 : RSM_WK0));
            uint32_t nxt = sbase + (cur ? RSM_WK0 : RSM_WK1);
            if (kc < 31) {
                const float* Wsrc = Wk + (size_t)(kc + 1) * 16 * HD;
                #pragma unroll
                for (int i = 0; i < 8; i++) {
                    int idx = i * 256 + t;
                    int r = idx >> 7;
                    int c4 = idx & 127;
                    cp_async16(nxt + r * 2048 + c4 * 16,
                               Wsrc + (size_t)r * HD + c4 * 4);
                }
                CP_COMMIT();
            }
            int kg = kc * 16;
            #pragma unroll
            for (int k = 0; k < 16; k++) {
                float w0 = wk[k * 512 + t];
                float w1 = wk[k * 512 + t + 256];
                #pragma unroll
                for (int g = 0; g < 8; g++) {
                    float x = vrow[g * 512 + kg + k];
                    a0[g] = fmaf(x, w0, a0[g]);
                    a1[g] = fmaf(x, w1, a1[g]);
                }
            }
            if (kc < 31) CP_WAIT0();
            __syncthreads();
        }

        #pragma unroll
        for (int g = 0; g < 8; g++) {
            float s = vv0 * tanh_fast(pq0 + a0[g]) + vv1 * tanh_fast(pq1 + a1[g]);
            #pragma unroll
            for (int off = 16; off > 0; off >>= 1)
                s += __shfl_xor_sync(0xffffffffu, s, off);
            if (lane == 0) red[g * 8 + wid] = s;
        }
        __syncthreads();
        if (t < 8) {
            int ci = base + t * 4;
            if (ci < cnt) {
                float s = 0.0f;
                #pragma unroll
                for (int w = 0; w < 8; w++) s += red[t * 8 + w];
                g_scores[head][b][g_cand[head][b][ci]] = s;
            }
        }
        __syncthreads();
    }
}

// ---------------------------------------------------------------------------
// Pass 2: register-resident bisect (30 iters) + compact context.
__global__ void sparsemax_kernel(const float* __restrict__ values_a,
                                 const float* __restrict__ values_b,
                                 float* __restrict__ out) {
    int head = blockIdx.x >> 5;
    int b    = blockIdx.x & 31;
    const float* V = head ? values_b : values_a;

    __shared__ float wred[16];
    __shared__ float bcast;
    __shared__ int   sidx[MAXCAND];
    __shared__ float sal[MAXCAND];
    __shared__ int   snum;

    int tid  = threadIdx.x;
    int lane = tid & 31;
    int wid  = tid >> 5;
    if (tid == 0) snum = 0;
    int i0 = tid * 8;

    float zr[8];
    {
        const float4* p = (const float4*)&g_scores[head][b][i0];
        float4 a = p[0], c = p[1];
        zr[0] = a.x; zr[1] = a.y; zr[2] = a.z; zr[3] = a.w;
        zr[4] = c.x; zr[5] = c.y; zr[6] = c.z; zr[7] = c.w;
    }

    float lmax = zr[0];
    #pragma unroll
    for (int j = 1; j < 8; j++) lmax = fmaxf(lmax, zr[j]);
    #pragma unroll
    for (int off = 16; off > 0; off >>= 1)
        lmax = fmaxf(lmax, __shfl_xor_sync(0xffffffffu, lmax, off));
    if (lane == 0) wred[wid] = lmax;
    __syncthreads();
    if (tid == 0) {
        float m = wred[0];
        for (int w = 1; w < 16; w++) m = fmaxf(m, wred[w]);
        bcast = m;
    }
    __syncthreads();
    float zmax = bcast;
    __syncthreads();

    float lo = zmax - 1.0f, hi = zmax;
    for (int it = 0; it < 30; it++) {
        float mid = 0.5f * (lo + hi);
        float s = 0.0f;
        #pragma unroll
        for (int j = 0; j < 8; j++) s += fmaxf(zr[j] - mid, 0.0f);
        float tot = block_sum(s, wred, &bcast, lane, wid, tid);
        if (tot >= 1.0f) lo = mid; else hi = mid;
    }
    float tau = 0.5f * (lo + hi);

    float* alout = out + OUT_AL + (size_t)head * BB * SS + (size_t)b * SS;
    float al[8];
    #pragma unroll
    for (int j = 0; j < 8; j++) al[j] = fmaxf(zr[j] - tau, 0.0f);
    {
        float4* q = (float4*)(alout + i0);
        q[0] = make_float4(al[0], al[1], al[2], al[3]);
        q[1] = make_float4(al[4], al[5], al[6], al[7]);
    }
    #pragma unroll
    for (int j = 0; j < 8; j++) {
        if (al[j] > 0.0f) {
            int p = atomicAdd(&snum, 1);
            if (p < MAXCAND) { sidx[p] = i0 + j; sal[p] = al[j]; }
        }
    }
    __syncthreads();

    const float* Vb = V + (size_t)b * SS * KD;
    float ctx = 0.0f;
    int ns = snum;
    if (ns <= MAXCAND) {
        for (int j = 0; j < ns; j++)
            ctx = fmaf(sal[j], Vb[(size_t)sidx[j] * KD + tid], ctx);
    } else {
        for (int s = 0; s < SS; s++) {
            float a = alout[s];
            if (a > 0.0f) ctx = fmaf(a, Vb[(size_t)s * KD + tid], ctx);
        }
    }
    g_ctx[head][b][tid] = ctx;
}

// ---------------------------------------------------------------------------
// Merge: gate softmax + candidates + blend. (h-quad x k-quarter) layout.
__global__ void merge_kernel(const float* __restrict__ query,
                             const float* __restrict__ Wg,
                             const float* __restrict__ bg,
                             const float* __restrict__ Wu_a,
                             const float* __restrict__ bu_a,
                             const float* __restrict__ Wu_b,
                             const float* __restrict__ bu_b,
                             float* __restrict__ out) {
    int b = blockIdx.x;
    int t = threadIdx.x;
    int lane = t & 31, wid = t >> 5;
    __shared__ float qv[HD], ca[KD], cb[KD];
    __shared__ float part_a[4][HD], part_b[4][HD];
    __shared__ float red0[16], red1[16];
    __shared__ float w01[2];

    qv[t] = query[b * HD + t];
    ca[t] = g_ctx[0][b][t];
    cb[t] = g_ctx[1][b][t];
    __syncthreads();

    float p0 = 0.0f, p1 = 0.0f;
    {
        float x = qv[t];
        p0 = fmaf(x, Wg[t * 2 + 0], p0);  p1 = fmaf(x, Wg[t * 2 + 1], p1);
        x = ca[t];
        p0 = fmaf(x, Wg[(512 + t) * 2 + 0], p0);  p1 = fmaf(x, Wg[(512 + t) * 2 + 1], p1);
        x = cb[t];
        p0 = fmaf(x, Wg[(1024 + t) * 2 + 0], p0); p1 = fmaf(x, Wg[(1024 + t) * 2 + 1], p1);
    }
    #pragma unroll
    for (int off = 16; off > 0; off >>= 1) {
        p0 += __shfl_xor_sync(0xffffffffu, p0, off);
        p1 += __shfl_xor_sync(0xffffffffu, p1, off);
    }
    if (lane == 0) { red0[wid] = p0; red1[wid] = p1; }
    __syncthreads();
    if (t == 0) {
        float g0 = bg[0], g1 = bg[1];
        for (int w = 0; w < 16; w++) { g0 += red0[w]; g1 += red1[w]; }
        float m = fmaxf(g0, g1);
        float e0 = expf(g0 - m), e1 = expf(g1 - m);
        float inv = 1.0f / (e0 + e1);
        w01[0] = e0 * inv;
        w01[1] = e1 * inv;
    }
    __syncthreads();

    int hq = (t & 127) * 4;
    int kq = t >> 7;
    const float* xa_seg = (kq < 2) ? (qv + kq * 256) : (ca + (kq - 2) * 256);
    const float* xb_seg = (kq < 2) ? (qv + kq * 256) : (cb + (kq - 2) * 256);
    const float* Wua = Wu_a + (size_t)(kq * 256) * HD + hq;
    const float* Wub = Wu_b + (size_t)(kq * 256) * HD + hq;
    float4 aa = make_float4(0.f, 0.f, 0.f, 0.f);
    float4 ab = make_float4(0.f, 0.f, 0.f, 0.f);
    #pragma unroll 2
    for (int i = 0; i < 256; i++) {
        float xa = xa_seg[i], xb = xb_seg[i];
        float4 wa = *(const float4*)(Wua + (size_t)i * HD);
        float4 wb = *(const float4*)(Wub + (size_t)i * HD);
        aa.x = fmaf(xa, wa.x, aa.x); aa.y = fmaf(xa, wa.y, aa.y);
        aa.z = fmaf(xa, wa.z, aa.z); aa.w = fmaf(xa, wa.w, aa.w);
        ab.x = fmaf(xb, wb.x, ab.x); ab.y = fmaf(xb, wb.y, ab.y);
        ab.z = fmaf(xb, wb.z, ab.z); ab.w = fmaf(xb, wb.w, ab.w);
    }
    *(float4*)&part_a[kq][hq] = aa;
    *(float4*)&part_b[kq][hq] = ab;
    __syncthreads();

    float w0 = w01[0], w1 = w01[1];
    float sa = bu_a[t] + (part_a[0][t] + part_a[1][t]) + (part_a[2][t] + part_a[3][t]);
    float sb = bu_b[t] + (part_b[0][t] + part_b[1][t]) + (part_b[2][t] + part_b[3][t]);
    out[OUT_ATT + b * HD + t] = w0 * tanhf(sa) + w1 * tanhf(sb);
}

// ---------------------------------------------------------------------------
extern "C" void kernel_launch(void* const* d_in, const int* in_sizes, int n_in,
                              void* d_out, int out_size) {
    const float* query    = (const float*)d_in[0];
    const float* values_a = (const float*)d_in[1];
    const float* values_b = (const float*)d_in[2];
    const void*  mask_a   = d_in[3];
    const void*  mask_b   = d_in[4];
    const float* Wk_a = (const float*)d_in[5];
    const float* Wq_a = (const float*)d_in[6];
    const float* v_a  = (const float*)d_in[7];
    const float* Wk_b = (const float*)d_in[8];
    const float* Wq_b = (const float*)d_in[9];
    const float* v_b  = (const float*)d_in[10];
    const float* Wg   = (const float*)d_in[11];
    const float* bg   = (const float*)d_in[12];
    const float* Wu_a = (const float*)d_in[13];
    const float* bu_a = (const float*)d_in[14];
    const float* Wu_b = (const float*)d_in[15];
    const float* bu_b = (const float*)d_in[16];
    float* out = (float*)d_out;

    cudaFuncSetAttribute(score_mma_kernel,
                         cudaFuncAttributeMaxDynamicSharedMemorySize, SM_TOTAL);
    cudaFuncSetAttribute(refine_kernel,
                         cudaFuncAttributeMaxDynamicSharedMemorySize, RSM_TOTAL);

    prep_all_kernel<<<PREP_GRID, 256>>>(query, values_a, values_b,
                                        (const unsigned char*)mask_a,
                                        Wk_a, Wk_b, Wq_a, Wq_b);
    dim3 g1(4, 32, 64);
    score_mma_kernel<<<g1, 256, SM_TOTAL>>>(v_a, v_b);
    spmax_pass1_kernel<<<64, 512>>>(mask_a, mask_b);
    refine_kernel<<<256, 256, RSM_TOTAL>>>(values_a, values_b, Wk_a, Wk_b,
                                           v_a, v_b);
    sparsemax_kernel<<<64, 512>>>(values_a, values_b, out);
    merge_kernel<<<32, 512>>>(query, Wg, bg, Wu_a, bu_a, Wu_b, bu_b, out);
}